// round 1
// baseline (speedup 1.0000x reference)
#include <cuda_runtime.h>
#include <cstdint>

#define CDIV(a,b) (((a)+(b)-1)/(b))

static constexpr int T_TOK = 8192;
static constexpr int DM    = 1024;
static constexpr int DFF   = 4096;
static constexpr int NE    = 8;
static constexpr int TOPK  = 2;
static constexpr int SLOTS = T_TOK * TOPK;   // 16384 routed token-slots

static constexpr int TM  = 128;   // M tile
static constexpr int TN  = 128;   // N tile
static constexpr int KC  = 16;    // K chunk per stage
static constexpr int PAD = 20;    // smem row stride in floats (conflict-free frag LDS)
static constexpr int MAXT = SLOTS/TM + NE;   // worst-case total M-tiles = 136

// ---- device scratch (no allocation allowed; __device__ globals are the sanctioned path) ----
__device__ int   g_cnt[NE];
__device__ int   g_base[NE];
__device__ int   g_toff[NE + 1];
__device__ int   g_tok[NE][SLOTS];
__device__ float g_wt[NE][SLOTS];
__device__ float g_h[(size_t)SLOTS * DFF];   // 268 MB intermediate activations

// ---------------------------------------------------------------- small kernels
__global__ void k_init() {
    if (threadIdx.x < NE) g_cnt[threadIdx.x] = 0;
}

__global__ void k_zero(float4* p, int n4) {
    int i = blockIdx.x * blockDim.x + threadIdx.x;
    if (i < n4) p[i] = make_float4(0.f, 0.f, 0.f, 0.f);
}

__global__ void k_route(const int* __restrict__ sel, const float* __restrict__ rw) {
    int s = blockIdx.x * blockDim.x + threadIdx.x;
    if (s >= SLOTS) return;
    const int* v = sel + (size_t)s * NE;     // one-hot row [NE]
    int e = 0;
    #pragma unroll
    for (int i = 1; i < NE; i++) if (v[i] != 0) e = i;
    int pos = atomicAdd(&g_cnt[e], 1);
    g_tok[e][pos] = s / TOPK;
    g_wt[e][pos]  = rw[s];
}

__global__ void k_sched() {
    int b = 0, t = 0;
    for (int e = 0; e < NE; e++) {
        g_base[e] = b;
        g_toff[e] = t;
        b += g_cnt[e];
        t += (g_cnt[e] + TM - 1) / TM;
    }
    g_toff[NE] = t;
}

// ---------------------------------------------------------------- mma helpers
__device__ __forceinline__ uint32_t f2tf(float f) {
    uint32_t u;
    asm("cvt.rna.tf32.f32 %0, %1;" : "=r"(u) : "f"(f));
    return u;
}

__device__ __forceinline__ void mma_tf32(float c[4], const uint32_t a[4], const uint32_t b[2]) {
    asm volatile(
        "mma.sync.aligned.m16n8k8.row.col.f32.tf32.tf32.f32 "
        "{%0,%1,%2,%3}, {%4,%5,%6,%7}, {%8,%9}, {%0,%1,%2,%3};"
        : "+f"(c[0]), "+f"(c[1]), "+f"(c[2]), "+f"(c[3])
        : "r"(a[0]), "r"(a[1]), "r"(a[2]), "r"(a[3]), "r"(b[0]), "r"(b[1]));
}

__device__ __forceinline__ void cpa16(float* dst, const float* src, bool p) {
    uint32_t s = (uint32_t)__cvta_generic_to_shared(dst);
    int sz = p ? 16 : 0;
    asm volatile("cp.async.cg.shared.global [%0], [%1], 16, %2;\n"
                 :: "r"(s), "l"(src), "r"(sz));
}

// ---------------------------------------------------------------- grouped GEMM
// FIRST:  h[slot, n] = relu( x[tok, :] . wi[e][n, :] ),  KD = DM,  N = DFF
// !FIRST: out[tok, n] += w * ( h[slot, :] . wo[e][n, :] ), KD = DFF, N = DM
template <bool FIRST, int KD>
__global__ __launch_bounds__(256) void k_gemm(const float* __restrict__ Xin,
                                              const float* __restrict__ Wm,
                                              float* __restrict__ Oout)
{
    __shared__ float sA[2][TM * PAD];
    __shared__ float sB[2][TN * PAD];

    const int Ntot = FIRST ? DFF : DM;

    int bx = blockIdx.x;
    int total = g_toff[NE];
    if (bx >= total) return;

    int e = 0;
    #pragma unroll
    for (int i = 1; i < NE; i++) if (bx >= g_toff[i]) e = i;
    int m0   = (bx - g_toff[e]) * TM;
    int cnt  = g_cnt[e];
    int base = g_base[e];
    int n0   = blockIdx.y * TN;

    int tid  = threadIdx.x;
    int lane = tid & 31, w = tid >> 5;
    int g = lane >> 2, t4 = lane & 3;

    // loader assignment: 2 threads per row, 8 floats (2x16B) each
    int lr = tid >> 1;
    int lc = (tid & 1) * 8;

    bool a_ok = (m0 + lr) < cnt;
    const float* aptr;
    if (FIRST) {
        int tok = a_ok ? g_tok[e][m0 + lr] : 0;
        aptr = Xin + (size_t)tok * KD;
    } else {
        aptr = &g_h[0] + (size_t)(base + m0 + lr) * KD;   // only read when a_ok
    }
    const float* bptr = Wm + ((size_t)e * Ntot + (n0 + lr)) * KD;

    float acc[2][8][4];
    #pragma unroll
    for (int i = 0; i < 2; i++)
        #pragma unroll
        for (int j = 0; j < 8; j++)
            #pragma unroll
            for (int q = 0; q < 4; q++) acc[i][j][q] = 0.f;

    const int NK = KD / KC;

    // prologue: stage 0
    #pragma unroll
    for (int c = 0; c < 2; c++) {
        cpa16(&sA[0][lr * PAD + lc + c * 4], aptr + lc + c * 4, a_ok);
        cpa16(&sB[0][lr * PAD + lc + c * 4], bptr + lc + c * 4, true);
    }
    asm volatile("cp.async.commit_group;\n");

    int wm0 = (w & 3) * 32, wn0 = (w >> 2) * 64;

    for (int kt = 0; kt < NK; kt++) {
        bool pf = (kt + 1) < NK;
        int  k1 = pf ? (kt + 1) * KC : 0;
        int  buf = kt & 1, nbuf = buf ^ 1;

        #pragma unroll
        for (int c = 0; c < 2; c++) {
            cpa16(&sA[nbuf][lr * PAD + lc + c * 4], aptr + k1 + lc + c * 4, pf && a_ok);
            cpa16(&sB[nbuf][lr * PAD + lc + c * 4], bptr + k1 + lc + c * 4, pf);
        }
        asm volatile("cp.async.commit_group;\n");
        asm volatile("cp.async.wait_group 1;\n");
        __syncthreads();

        #pragma unroll
        for (int kk = 0; kk < KC; kk += 8) {
            uint32_t af[2][4];
            #pragma unroll
            for (int ms = 0; ms < 2; ms++) {
                int r = wm0 + ms * 16;
                af[ms][0] = f2tf(sA[buf][(r + g    ) * PAD + kk + t4]);
                af[ms][1] = f2tf(sA[buf][(r + 8 + g) * PAD + kk + t4]);
                af[ms][2] = f2tf(sA[buf][(r + g    ) * PAD + kk + 4 + t4]);
                af[ms][3] = f2tf(sA[buf][(r + 8 + g) * PAD + kk + 4 + t4]);
            }
            uint32_t bf[8][2];
            #pragma unroll
            for (int ns = 0; ns < 8; ns++) {
                int c = wn0 + ns * 8;
                bf[ns][0] = f2tf(sB[buf][(c + g) * PAD + kk + t4]);
                bf[ns][1] = f2tf(sB[buf][(c + g) * PAD + kk + 4 + t4]);
            }
            #pragma unroll
            for (int ms = 0; ms < 2; ms++)
                #pragma unroll
                for (int ns = 0; ns < 8; ns++)
                    mma_tf32(acc[ms][ns], af[ms], bf[ns]);
        }
        __syncthreads();
    }

    // epilogue
    #pragma unroll
    for (int ms = 0; ms < 2; ms++) {
        int r0 = wm0 + ms * 16 + g;
        #pragma unroll
        for (int half = 0; half < 2; half++) {
            int lrow = r0 + half * 8;
            int mrow = m0 + lrow;
            if (mrow < cnt) {
                if (FIRST) {
                    float* hp = &g_h[0] + (size_t)(base + mrow) * DFF + n0 + wn0;
                    #pragma unroll
                    for (int ns = 0; ns < 8; ns++) {
                        float v0 = acc[ms][ns][half * 2 + 0];
                        float v1 = acc[ms][ns][half * 2 + 1];
                        float2 st = make_float2(fmaxf(v0, 0.f), fmaxf(v1, 0.f));
                        *reinterpret_cast<float2*>(hp + ns * 8 + 2 * t4) = st;
                    }
                } else {
                    int   tok = g_tok[e][mrow];
                    float wgt = g_wt[e][mrow];
                    float* op = Oout + (size_t)tok * DM + n0 + wn0;
                    #pragma unroll
                    for (int ns = 0; ns < 8; ns++) {
                        atomicAdd(op + ns * 8 + 2 * t4,     wgt * acc[ms][ns][half * 2 + 0]);
                        atomicAdd(op + ns * 8 + 2 * t4 + 1, wgt * acc[ms][ns][half * 2 + 1]);
                    }
                }
            }
        }
    }
}

// ---------------------------------------------------------------- launch
extern "C" void kernel_launch(void* const* d_in, const int* in_sizes, int n_in,
                              void* d_out, int out_size)
{
    const float* x   = (const float*)d_in[0];   // [T, DM]
    const int*   sel = (const int*)  d_in[1];   // [T, K, E] one-hot int32
    const float* rw  = (const float*)d_in[2];   // [T, K]
    const float* wi  = (const float*)d_in[3];   // [E, DFF, DM]
    const float* wo  = (const float*)d_in[4];   // [E, DM, DFF]
    float* out = (float*)d_out;                 // [T, DM]

    k_init<<<1, 32>>>();
    int n4 = out_size / 4;
    k_zero<<<CDIV(n4, 256), 256>>>((float4*)out, n4);
    k_route<<<CDIV(SLOTS, 256), 256>>>(sel, rw);
    k_sched<<<1, 1>>>();

    k_gemm<true,  DM ><<<dim3(MAXT, DFF / TN), 256>>>(x, wi, nullptr);
    k_gemm<false, DFF><<<dim3(MAXT, DM  / TN), 256>>>(nullptr, wo, out);
}